// round 8
// baseline (speedup 1.0000x reference)
#include <cuda_runtime.h>
#include <cuda_bf16.h>
#include <math.h>

// Problem dims
#define TT   128
#define BB   256
#define NN   (TT*BB)        // 32768
#define HID  128
#define G4   512            // 4*HID
#define NFLAT 1024
#define NA   7

// ---------------- scratch (device globals, no allocation) ----------------
__device__ __align__(16) float g_feat[NN * NFLAT];   // tf32-rounded fp32
__device__ __align__(16) float g_pre [NN * G4];
__device__ __align__(16) float g_hid [NN * HID];
__device__ __align__(16) float g_wih [G4 * NFLAT];   // tf32-rounded fp32
__device__ __align__(16) float g_bias[G4];

__device__ __forceinline__ unsigned f2tf(float f) {
    unsigned u;
    asm("cvt.rna.tf32.f32 %0, %1;" : "=r"(u) : "f"(f));
    return u;
}
__device__ __forceinline__ unsigned smem_u32(const void* p) {
    unsigned r;
    asm("{ .reg .u64 t; cvta.to.shared.u64 t, %1; cvt.u32.u64 %0, t; }" : "=r"(r) : "l"(p));
    return r;
}
// MUFU-based tanh, overflow-safe: tanh(x) = sign(x) * (1 - t)/(1 + t), t = exp(-2|x|)
__device__ __forceinline__ float fast_tanh(float x) {
    float t = __expf(-2.f * fabsf(x));
    float r = __fdividef(1.f - t, 1.f + t);
    return copysignf(r, x);
}
__device__ __forceinline__ float fast_sigmoid(float x) {
    return __fdividef(1.f, 1.f + __expf(-x));
}

// ---------------- Kernel 0: prep (tf32 weights + fused bias) ----------------
__global__ __launch_bounds__(256) void prep_kernel(
    const float* __restrict__ wih,
    const float* __restrict__ bih, const float* __restrict__ bhh)
{
    int i = blockIdx.x * 256 + threadIdx.x;
    if (i < G4 * NFLAT) g_wih[i] = __uint_as_float(f2tf(wih[i]));
    if (i < G4)         g_bias[i] = bih[i] + bhh[i];
}

// ---------------- Kernel 1: conv stack; conv3 via tf32 mma ----------------
#define CV_XS 0
#define CV_C1 588
#define CV_S1 577
#define CV_C2 2896
#define CV_S2 801
#define CV_W2 6100
#define CV_A  8148
#define CV_B  16596
#define CV_SMEM_FLOATS (CV_B + 64*132)
#define CV_SMEM_BYTES  (CV_SMEM_FLOATS * 4)   // ~100 KB

__global__ __launch_bounds__(256) void conv_feat_kernel(
    const float* __restrict__ obs,
    const float* __restrict__ w1, const float* __restrict__ b1,
    const float* __restrict__ w2, const float* __restrict__ b2,
    const float* __restrict__ w3, const float* __restrict__ b3)
{
    extern __shared__ __align__(16) float sm[];
    const int tid = threadIdx.x;
    const int n0 = blockIdx.x * 4;

    {
        const float4* s2 = (const float4*)w2;
        float4* d2 = (float4*)(sm + CV_W2);
        for (int i = tid; i < 32*16; i += 256) d2[i] = s2[i];
        for (int i = tid; i < 64*128; i += 256) {
            int o = i >> 7, col = i & 127;
            sm[CV_B + o*132 + col] = __uint_as_float(f2tf(w3[i]));
        }
    }
    for (int i = tid; i < 4*147; i += 256) {
        int s = i / 147, r = i % 147;
        int h = r / 21, q = r % 21, w = q / 3, c = q % 3;
        sm[CV_XS + s*147 + c*49 + h*7 + w] = obs[(size_t)n0 * 147 + i];
    }
    __syncthreads();

    // conv1: 16 x 6x6, 3ch 2x2 (fp32)
    for (int i = tid; i < 4*576; i += 256) {
        int s = i / 576, r = i % 576;
        int o = r / 36, q = r % 36, y = q / 6, x = q % 6;
        float acc = __ldg(&b1[o]);
        #pragma unroll
        for (int c = 0; c < 3; c++) {
            float4 wv = *(const float4*)&w1[(o*3 + c) * 4];
            const float* xb = sm + CV_XS + s*147 + c*49 + y*7 + x;
            acc += xb[0] * wv.x + xb[1] * wv.y + xb[7] * wv.z + xb[8] * wv.w;
        }
        sm[CV_C1 + s*CV_S1 + o*36 + y*6 + x] = fmaxf(acc, 0.f);
    }
    __syncthreads();

    // conv2: 32 x 5x5, 16ch 2x2 (fp32)
    if (tid < 200) {
        int oh = tid / 100, rem = tid % 100;
        int pos = rem >> 2, s = rem & 3;
        int y = pos / 5, x = pos % 5;
        int o0 = oh * 16;
        float acc[16];
        #pragma unroll
        for (int o = 0; o < 16; o++) acc[o] = __ldg(&b2[o0 + o]);
        const float4* w2v = (const float4*)(sm + CV_W2);
        #pragma unroll 4
        for (int c = 0; c < 16; c++) {
            const float* xb = sm + CV_C1 + s*CV_S1 + c*36 + y*6 + x;
            float aa = xb[0], ab = xb[1], ac = xb[6], ad = xb[7];
            #pragma unroll
            for (int o = 0; o < 16; o++) {
                float4 wv = w2v[(o0 + o)*16 + c];
                acc[o] += aa*wv.x + ab*wv.y + ac*wv.z + ad*wv.w;
            }
        }
        #pragma unroll
        for (int o = 0; o < 16; o++)
            sm[CV_C2 + s*CV_S2 + (o0 + o)*25 + pos] = fmaxf(acc[o], 0.f);
    }
    __syncthreads();

    // im2col for conv3
    for (int i = tid; i < 64*128; i += 256) {
        int row = i >> 7, col = i & 127;
        int s = row >> 4, pos = row & 15, y = pos >> 2, x = pos & 3;
        int c = col >> 2, j = col & 3, dy = j >> 1, dx = j & 1;
        float v = sm[CV_C2 + s*CV_S2 + c*25 + (y+dy)*5 + (x+dx)];
        sm[CV_A + row*132 + col] = __uint_as_float(f2tf(v));
    }
    __syncthreads();

    // conv3 mma: [64x64] = A[64x128] @ B^T, m16n8k8 tf32
    {
        const int lane = tid & 31, wid = tid >> 5;
        const int lr = lane >> 2, lc = lane & 3;
        const int wm = wid & 1, wn = wid >> 1;
        const unsigned* As = (const unsigned*)(sm + CV_A);
        const unsigned* Bs = (const unsigned*)(sm + CV_B);

        float acc[2][2][4];
        #pragma unroll
        for (int mt = 0; mt < 2; mt++)
            #pragma unroll
            for (int nt = 0; nt < 2; nt++)
                #pragma unroll
                for (int r = 0; r < 4; r++) acc[mt][nt][r] = 0.f;

        #pragma unroll 4
        for (int ks = 0; ks < 16; ks++) {
            const int k0 = ks * 8;
            unsigned a[2][4], b[2][2];
            #pragma unroll
            for (int mt = 0; mt < 2; mt++) {
                int m0 = wm * 32 + mt * 16;
                a[mt][0] = As[(m0 + lr    ) * 132 + k0 + lc    ];
                a[mt][1] = As[(m0 + lr + 8) * 132 + k0 + lc    ];
                a[mt][2] = As[(m0 + lr    ) * 132 + k0 + lc + 4];
                a[mt][3] = As[(m0 + lr + 8) * 132 + k0 + lc + 4];
            }
            #pragma unroll
            for (int nt = 0; nt < 2; nt++) {
                int nr = wn * 16 + nt * 8;
                b[nt][0] = Bs[(nr + lr) * 132 + k0 + lc    ];
                b[nt][1] = Bs[(nr + lr) * 132 + k0 + lc + 4];
            }
            #pragma unroll
            for (int mt = 0; mt < 2; mt++)
                #pragma unroll
                for (int nt = 0; nt < 2; nt++) {
                    asm volatile(
                        "mma.sync.aligned.m16n8k8.row.col.f32.tf32.tf32.f32 "
                        "{%0,%1,%2,%3}, {%4,%5,%6,%7}, {%8,%9}, {%0,%1,%2,%3};\n"
                        : "+f"(acc[mt][nt][0]), "+f"(acc[mt][nt][1]),
                          "+f"(acc[mt][nt][2]), "+f"(acc[mt][nt][3])
                        : "r"(a[mt][0]), "r"(a[mt][1]), "r"(a[mt][2]), "r"(a[mt][3]),
                          "r"(b[nt][0]), "r"(b[nt][1]));
                }
        }

        #pragma unroll
        for (int mt = 0; mt < 2; mt++) {
            #pragma unroll
            for (int nt = 0; nt < 2; nt++) {
                int o = wn * 16 + nt * 8 + 2 * lc;
                float bo0 = __ldg(&b3[o]), bo1 = __ldg(&b3[o + 1]);
                #pragma unroll
                for (int rr = 0; rr < 2; rr++) {
                    int row = wm * 32 + mt * 16 + lr + rr * 8;
                    int s = row >> 4, pos = row & 15;
                    float* fo = g_feat + (size_t)(n0 + s) * NFLAT;
                    float v0 = fmaxf(acc[mt][nt][rr * 2    ] + bo0, 0.f);
                    float v1 = fmaxf(acc[mt][nt][rr * 2 + 1] + bo1, 0.f);
                    fo[o * 16 + pos]       = __uint_as_float(f2tf(v0));
                    fo[(o + 1) * 16 + pos] = __uint_as_float(f2tf(v1));
                }
            }
        }
    }
}

// ---------------- Kernel 2: tf32 tensor-core GEMM, 3-stage cp.async ----------------
#define GSTAGE 3
#define GSTRIDE 2560
#define G_SMEM_BYTES (GSTAGE * 2 * GSTRIDE * 4)

__global__ __launch_bounds__(256, 2) void gemm_pre_kernel()
{
    extern __shared__ __align__(16) unsigned smg[];
    unsigned* sA = smg;
    unsigned* sB = smg + GSTAGE * GSTRIDE;

    const int tid  = threadIdx.x;
    const int lane = tid & 31;
    const int wid  = tid >> 5;
    const int lr = lane >> 2, lc = lane & 3;
    const int wm = wid & 1;
    const int wn = wid >> 1;
    const int row0 = blockIdx.y * 128;
    const int col0 = blockIdx.x * 128;

    const unsigned baseA = smem_u32(sA);
    const unsigned baseB = smem_u32(sB);

    int sm0 = (tid        ) >> 2, sk0 = ((tid      ) & 3) * 4;
    int sm1 = (tid + 256  ) >> 2, sk1 = ((tid + 256) & 3) * 4;

    float acc[4][4][4];
    #pragma unroll
    for (int mt = 0; mt < 4; mt++)
        #pragma unroll
        for (int nt = 0; nt < 4; nt++)
            #pragma unroll
            for (int r = 0; r < 4; r++) acc[mt][nt][r] = 0.f;

    #define G_ISSUE(s, kt)                                                          \
    {                                                                               \
        const float* ga0 = g_feat + (size_t)(row0 + sm0) * NFLAT + (kt) + sk0;      \
        const float* ga1 = g_feat + (size_t)(row0 + sm1) * NFLAT + (kt) + sk1;      \
        const float* gb0 = g_wih  + (size_t)(col0 + sm0) * NFLAT + (kt) + sk0;      \
        const float* gb1 = g_wih  + (size_t)(col0 + sm1) * NFLAT + (kt) + sk1;      \
        unsigned da0 = baseA + ((s)*GSTRIDE + sm0*20 + sk0) * 4;                    \
        unsigned da1 = baseA + ((s)*GSTRIDE + sm1*20 + sk1) * 4;                    \
        unsigned db0 = baseB + ((s)*GSTRIDE + sm0*20 + sk0) * 4;                    \
        unsigned db1 = baseB + ((s)*GSTRIDE + sm1*20 + sk1) * 4;                    \
        asm volatile("cp.async.cg.shared.global [%0], [%1], 16;" :: "r"(da0), "l"(ga0)); \
        asm volatile("cp.async.cg.shared.global [%0], [%1], 16;" :: "r"(da1), "l"(ga1)); \
        asm volatile("cp.async.cg.shared.global [%0], [%1], 16;" :: "r"(db0), "l"(gb0)); \
        asm volatile("cp.async.cg.shared.global [%0], [%1], 16;" :: "r"(db1), "l"(gb1)); \
    }

    G_ISSUE(0, 0);
    asm volatile("cp.async.commit_group;");
    G_ISSUE(1, 16);
    asm volatile("cp.async.commit_group;");

    const int NIT = NFLAT / 16;
    for (int it = 0; it < NIT; it++) {
        const int s = it % GSTAGE;
        asm volatile("cp.async.wait_group 1;");
        __syncthreads();
        if (it + 2 < NIT) {
            G_ISSUE((it + 2) % GSTAGE, (it + 2) * 16);
        }
        asm volatile("cp.async.commit_group;");

        const unsigned* pA = sA + s * GSTRIDE;
        const unsigned* pB = sB + s * GSTRIDE;
        #pragma unroll
        for (int ks = 0; ks < 2; ks++) {
            const int k0 = ks * 8;
            unsigned a[4][4], b[4][2];
            #pragma unroll
            for (int mt = 0; mt < 4; mt++) {
                int m0 = wm * 64 + mt * 16;
                a[mt][0] = pA[(m0 + lr    ) * 20 + k0 + lc    ];
                a[mt][1] = pA[(m0 + lr + 8) * 20 + k0 + lc    ];
                a[mt][2] = pA[(m0 + lr    ) * 20 + k0 + lc + 4];
                a[mt][3] = pA[(m0 + lr + 8) * 20 + k0 + lc + 4];
            }
            #pragma unroll
            for (int nt = 0; nt < 4; nt++) {
                int n0 = wn * 32 + nt * 8;
                b[nt][0] = pB[(n0 + lr) * 20 + k0 + lc    ];
                b[nt][1] = pB[(n0 + lr) * 20 + k0 + lc + 4];
            }
            #pragma unroll
            for (int mt = 0; mt < 4; mt++)
                #pragma unroll
                for (int nt = 0; nt < 4; nt++) {
                    asm volatile(
                        "mma.sync.aligned.m16n8k8.row.col.f32.tf32.tf32.f32 "
                        "{%0,%1,%2,%3}, {%4,%5,%6,%7}, {%8,%9}, {%0,%1,%2,%3};\n"
                        : "+f"(acc[mt][nt][0]), "+f"(acc[mt][nt][1]),
                          "+f"(acc[mt][nt][2]), "+f"(acc[mt][nt][3])
                        : "r"(a[mt][0]), "r"(a[mt][1]), "r"(a[mt][2]), "r"(a[mt][3]),
                          "r"(b[nt][0]), "r"(b[nt][1]));
                }
        }
    }

    float bb0[4], bb1[4];
    #pragma unroll
    for (int nt = 0; nt < 4; nt++) {
        int col = col0 + wn * 32 + nt * 8 + 2 * lc;
        bb0[nt] = g_bias[col];
        bb1[nt] = g_bias[col + 1];
    }
    #pragma unroll
    for (int mt = 0; mt < 4; mt++) {
        int r0 = row0 + wm * 64 + mt * 16 + lr;
        #pragma unroll
        for (int nt = 0; nt < 4; nt++) {
            int col = col0 + wn * 32 + nt * 8 + 2 * lc;
            *(float2*)&g_pre[(size_t)r0 * G4 + col] =
                make_float2(acc[mt][nt][0] + bb0[nt], acc[mt][nt][1] + bb1[nt]);
            *(float2*)&g_pre[(size_t)(r0 + 8) * G4 + col] =
                make_float2(acc[mt][nt][2] + bb0[nt], acc[mt][nt][3] + bb1[nt]);
        }
    }
}

// ---------------- Kernel 3: persistent LSTM ----------------
// float4 hs loads with ONLY 2 accumulators (R5's spill came from the 8
// accumulator chains on top of wc[64]; this keeps peak regs ~95 < 128).
#define RC 64
__global__ __launch_bounds__(512, 1) void lstm_kernel(
    const float* __restrict__ done,
    const float* __restrict__ h0, const float* __restrict__ c0,
    const float* __restrict__ w_hh,
    float* __restrict__ hT, float* __restrict__ cT)
{
    __shared__ __align__(16) float hs[2][128];
    __shared__ __align__(16) float cs[2][128];
    __shared__ float gs[2][512];

    const int tid = threadIdx.x;
    const int b0  = blockIdx.x * 2;

    if (tid < 256) {
        int r = tid >> 7, u = tid & 127;
        float m = 1.f - done[b0 + r];
        hs[r][u] = h0[(b0 + r) * HID + u] * m;
        cs[r][u] = c0[(b0 + r) * HID + u] * m;
    }

    const float* wrow = w_hh + (size_t)tid * HID;
    float wc[RC];
    #pragma unroll
    for (int k = 0; k < RC; k++) wc[k] = wrow[k];
    __syncthreads();

    float a0 = g_pre[(size_t)b0 * G4 + tid];
    float a1 = g_pre[(size_t)(b0 + 1) * G4 + tid];

    for (int t = 0; t < TT; t++) {
        #pragma unroll
        for (int k = 0; k < RC; k += 4) {
            float4 h0v = *(const float4*)&hs[0][k];
            float4 h1v = *(const float4*)&hs[1][k];
            a0 = fmaf(wc[k    ], h0v.x, a0);
            a0 = fmaf(wc[k + 1], h0v.y, a0);
            a0 = fmaf(wc[k + 2], h0v.z, a0);
            a0 = fmaf(wc[k + 3], h0v.w, a0);
            a1 = fmaf(wc[k    ], h1v.x, a1);
            a1 = fmaf(wc[k + 1], h1v.y, a1);
            a1 = fmaf(wc[k + 2], h1v.z, a1);
            a1 = fmaf(wc[k + 3], h1v.w, a1);
        }
        #pragma unroll
        for (int k = RC; k < HID; k += 4) {
            float4 wv  = *(const float4*)(wrow + k);
            float4 h0v = *(const float4*)&hs[0][k];
            float4 h1v = *(const float4*)&hs[1][k];
            a0 = fmaf(wv.x, h0v.x, a0);
            a0 = fmaf(wv.y, h0v.y, a0);
            a0 = fmaf(wv.z, h0v.z, a0);
            a0 = fmaf(wv.w, h0v.w, a0);
            a1 = fmaf(wv.x, h1v.x, a1);
            a1 = fmaf(wv.y, h1v.y, a1);
            a1 = fmaf(wv.z, h1v.z, a1);
            a1 = fmaf(wv.w, h1v.w, a1);
        }
        gs[0][tid] = a0;
        gs[1][tid] = a1;

        if (t + 1 < TT) {
            a0 = g_pre[((size_t)((t + 1) * BB + b0    )) * G4 + tid];
            a1 = g_pre[((size_t)((t + 1) * BB + b0 + 1)) * G4 + tid];
        }
        __syncthreads();

        if (tid < 256) {
            int r = tid >> 7, u = tid & 127;
            float ig = fast_sigmoid(gs[r][u]);
            float fg = fast_sigmoid(gs[r][128 + u]);
            float gg = fast_tanh(gs[r][256 + u]);
            float og = fast_sigmoid(gs[r][384 + u]);
            float c = fg * cs[r][u] + ig * gg;
            float h = og * fast_tanh(c);
            g_hid[((size_t)(t * BB + b0 + r)) * HID + u] = h;
            float m = (t + 1 < TT) ? (1.f - done[(t + 1) * BB + b0 + r]) : 1.f;
            cs[r][u] = c * m;
            hs[r][u] = h * m;
        }
        __syncthreads();
    }

    if (tid < 256) {
        int r = tid >> 7, u = tid & 127;
        hT[(b0 + r) * HID + u] = hs[r][u];
        cT[(b0 + r) * HID + u] = cs[r][u];
    }
}

// ---------------- Kernel 4: heads -> out[N,8] ----------------
__global__ __launch_bounds__(128) void heads_kernel(
    const float* __restrict__ aw, const float* __restrict__ ab,
    const float* __restrict__ cw, const float* __restrict__ cb,
    float* __restrict__ out)
{
    __shared__ __align__(16) float ws [8][132];
    __shared__ __align__(16) float hsm[16][132];
    __shared__ float bs[8];

    const int tid = threadIdx.x;
    const int n0 = blockIdx.x * 16;

    for (int i = tid; i < NA * HID; i += 128) ws[i >> 7][i & 127] = aw[i];
    ws[7][tid] = cw[tid];
    if (tid < NA) bs[tid] = ab[tid];
    if (tid == NA) bs[7] = cb[0];

    for (int i = tid; i < 16 * HID; i += 128)
        hsm[i >> 7][i & 127] = g_hid[(size_t)n0 * HID + i];
    __syncthreads();

    const int s = tid >> 3, col = tid & 7;
    float acc = bs[col];
    const float4* hp = (const float4*)&hsm[s][0];
    const float4* wp = (const float4*)&ws[col][0];
    #pragma unroll
    for (int k = 0; k < 32; k++) {
        float4 h4 = hp[k], w4 = wp[k];
        acc += h4.x * w4.x + h4.y * w4.y + h4.z * w4.z + h4.w * w4.w;
    }
    out[(size_t)(n0 + s) * 8 + col] = acc;
}

// ---------------- launch ----------------
extern "C" void kernel_launch(void* const* d_in, const int* in_sizes, int n_in,
                              void* d_out, int out_size)
{
    const float* obs   = (const float*)d_in[0];
    const float* done  = (const float*)d_in[1];
    const float* h0    = (const float*)d_in[2];
    const float* c0    = (const float*)d_in[3];
    const float* w1    = (const float*)d_in[4];
    const float* b1    = (const float*)d_in[5];
    const float* w2    = (const float*)d_in[6];
    const float* b2    = (const float*)d_in[7];
    const float* w3    = (const float*)d_in[8];
    const float* b3    = (const float*)d_in[9];
    const float* w_ih  = (const float*)d_in[10];
    const float* w_hh  = (const float*)d_in[11];
    const float* b_ih  = (const float*)d_in[12];
    const float* b_hh  = (const float*)d_in[13];
    const float* aw    = (const float*)d_in[14];
    const float* ab    = (const float*)d_in[15];
    const float* cw    = (const float*)d_in[16];
    const float* cb    = (const float*)d_in[17];

    float* out = (float*)d_out;                    // [N, 8]
    float* hT  = out + (size_t)NN * 8;             // [B, HID]
    float* cT  = hT + (size_t)BB * HID;            // [B, HID]

    static bool attr_done = false;
    if (!attr_done) {
        cudaFuncSetAttribute(conv_feat_kernel,
                             cudaFuncAttributeMaxDynamicSharedMemorySize,
                             CV_SMEM_BYTES);
        cudaFuncSetAttribute(gemm_pre_kernel,
                             cudaFuncAttributeMaxDynamicSharedMemorySize,
                             G_SMEM_BYTES);
        attr_done = true;
    }

    prep_kernel<<<(G4 * NFLAT + 255) / 256, 256>>>(w_ih, b_ih, b_hh);

    conv_feat_kernel<<<NN / 4, 256, CV_SMEM_BYTES>>>(obs, w1, b1, w2, b2, w3, b3);

    dim3 ggrid(G4 / 128, NN / 128);
    gemm_pre_kernel<<<ggrid, 256, G_SMEM_BYTES>>>();

    lstm_kernel<<<BB / 2, 512>>>(done, h0, c0, w_hh, hT, cT);

    heads_kernel<<<NN / 16, 128>>>(aw, ab, cw, cb, out);
}

// round 9
// speedup vs baseline: 1.0005x; 1.0005x over previous
#include <cuda_runtime.h>
#include <cuda_bf16.h>
#include <math.h>

// Problem dims
#define TT   128
#define BB   256
#define NN   (TT*BB)        // 32768
#define HID  128
#define G4   512            // 4*HID
#define NFLAT 1024
#define NA   7

// ---------------- scratch (device globals, no allocation) ----------------
__device__ __align__(16) float g_feat[NN * NFLAT];   // tf32-rounded fp32
__device__ __align__(16) float g_pre [NN * G4];
__device__ __align__(16) float g_hid [NN * HID];
__device__ __align__(16) float g_wih [G4 * NFLAT];   // tf32-rounded fp32
__device__ __align__(16) float g_bias[G4];

__device__ __forceinline__ unsigned f2tf(float f) {
    unsigned u;
    asm("cvt.rna.tf32.f32 %0, %1;" : "=r"(u) : "f"(f));
    return u;
}
__device__ __forceinline__ unsigned smem_u32(const void* p) {
    unsigned r;
    asm("{ .reg .u64 t; cvta.to.shared.u64 t, %1; cvt.u32.u64 %0, t; }" : "=r"(r) : "l"(p));
    return r;
}
// MUFU-based tanh, overflow-safe: tanh(x) = sign(x) * (1 - t)/(1 + t), t = exp(-2|x|)
__device__ __forceinline__ float fast_tanh(float x) {
    float t = __expf(-2.f * fabsf(x));
    float r = __fdividef(1.f - t, 1.f + t);
    return copysignf(r, x);
}
__device__ __forceinline__ float fast_sigmoid(float x) {
    return __fdividef(1.f, 1.f + __expf(-x));
}

// ---------------- Kernel 0: prep (tf32 weights + fused bias) ----------------
__global__ __launch_bounds__(256) void prep_kernel(
    const float* __restrict__ wih,
    const float* __restrict__ bih, const float* __restrict__ bhh)
{
    int i = blockIdx.x * 256 + threadIdx.x;
    if (i < G4 * NFLAT) g_wih[i] = __uint_as_float(f2tf(wih[i]));
    if (i < G4)         g_bias[i] = bih[i] + bhh[i];
}

// ---------------- Kernel 1: conv stack; conv3 via tf32 mma ----------------
#define CV_XS 0
#define CV_C1 588
#define CV_S1 577
#define CV_C2 2896
#define CV_S2 801
#define CV_W2 6100
#define CV_A  8148
#define CV_B  16596
#define CV_SMEM_FLOATS (CV_B + 64*132)
#define CV_SMEM_BYTES  (CV_SMEM_FLOATS * 4)   // ~100 KB

__global__ __launch_bounds__(256) void conv_feat_kernel(
    const float* __restrict__ obs,
    const float* __restrict__ w1, const float* __restrict__ b1,
    const float* __restrict__ w2, const float* __restrict__ b2,
    const float* __restrict__ w3, const float* __restrict__ b3)
{
    extern __shared__ __align__(16) float sm[];
    const int tid = threadIdx.x;
    const int n0 = blockIdx.x * 4;

    {
        const float4* s2 = (const float4*)w2;
        float4* d2 = (float4*)(sm + CV_W2);
        for (int i = tid; i < 32*16; i += 256) d2[i] = s2[i];
        for (int i = tid; i < 64*128; i += 256) {
            int o = i >> 7, col = i & 127;
            sm[CV_B + o*132 + col] = __uint_as_float(f2tf(w3[i]));
        }
    }
    for (int i = tid; i < 4*147; i += 256) {
        int s = i / 147, r = i % 147;
        int h = r / 21, q = r % 21, w = q / 3, c = q % 3;
        sm[CV_XS + s*147 + c*49 + h*7 + w] = obs[(size_t)n0 * 147 + i];
    }
    __syncthreads();

    // conv1: 16 x 6x6, 3ch 2x2 (fp32)
    for (int i = tid; i < 4*576; i += 256) {
        int s = i / 576, r = i % 576;
        int o = r / 36, q = r % 36, y = q / 6, x = q % 6;
        float acc = __ldg(&b1[o]);
        #pragma unroll
        for (int c = 0; c < 3; c++) {
            float4 wv = *(const float4*)&w1[(o*3 + c) * 4];
            const float* xb = sm + CV_XS + s*147 + c*49 + y*7 + x;
            acc += xb[0] * wv.x + xb[1] * wv.y + xb[7] * wv.z + xb[8] * wv.w;
        }
        sm[CV_C1 + s*CV_S1 + o*36 + y*6 + x] = fmaxf(acc, 0.f);
    }
    __syncthreads();

    // conv2: 32 x 5x5, 16ch 2x2 (fp32)
    if (tid < 200) {
        int oh = tid / 100, rem = tid % 100;
        int pos = rem >> 2, s = rem & 3;
        int y = pos / 5, x = pos % 5;
        int o0 = oh * 16;
        float acc[16];
        #pragma unroll
        for (int o = 0; o < 16; o++) acc[o] = __ldg(&b2[o0 + o]);
        const float4* w2v = (const float4*)(sm + CV_W2);
        #pragma unroll 4
        for (int c = 0; c < 16; c++) {
            const float* xb = sm + CV_C1 + s*CV_S1 + c*36 + y*6 + x;
            float aa = xb[0], ab = xb[1], ac = xb[6], ad = xb[7];
            #pragma unroll
            for (int o = 0; o < 16; o++) {
                float4 wv = w2v[(o0 + o)*16 + c];
                acc[o] += aa*wv.x + ab*wv.y + ac*wv.z + ad*wv.w;
            }
        }
        #pragma unroll
        for (int o = 0; o < 16; o++)
            sm[CV_C2 + s*CV_S2 + (o0 + o)*25 + pos] = fmaxf(acc[o], 0.f);
    }
    __syncthreads();

    // im2col for conv3
    for (int i = tid; i < 64*128; i += 256) {
        int row = i >> 7, col = i & 127;
        int s = row >> 4, pos = row & 15, y = pos >> 2, x = pos & 3;
        int c = col >> 2, j = col & 3, dy = j >> 1, dx = j & 1;
        float v = sm[CV_C2 + s*CV_S2 + c*25 + (y+dy)*5 + (x+dx)];
        sm[CV_A + row*132 + col] = __uint_as_float(f2tf(v));
    }
    __syncthreads();

    // conv3 mma: [64x64] = A[64x128] @ B^T, m16n8k8 tf32
    {
        const int lane = tid & 31, wid = tid >> 5;
        const int lr = lane >> 2, lc = lane & 3;
        const int wm = wid & 1, wn = wid >> 1;
        const unsigned* As = (const unsigned*)(sm + CV_A);
        const unsigned* Bs = (const unsigned*)(sm + CV_B);

        float acc[2][2][4];
        #pragma unroll
        for (int mt = 0; mt < 2; mt++)
            #pragma unroll
            for (int nt = 0; nt < 2; nt++)
                #pragma unroll
                for (int r = 0; r < 4; r++) acc[mt][nt][r] = 0.f;

        #pragma unroll 4
        for (int ks = 0; ks < 16; ks++) {
            const int k0 = ks * 8;
            unsigned a[2][4], b[2][2];
            #pragma unroll
            for (int mt = 0; mt < 2; mt++) {
                int m0 = wm * 32 + mt * 16;
                a[mt][0] = As[(m0 + lr    ) * 132 + k0 + lc    ];
                a[mt][1] = As[(m0 + lr + 8) * 132 + k0 + lc    ];
                a[mt][2] = As[(m0 + lr    ) * 132 + k0 + lc + 4];
                a[mt][3] = As[(m0 + lr + 8) * 132 + k0 + lc + 4];
            }
            #pragma unroll
            for (int nt = 0; nt < 2; nt++) {
                int nr = wn * 16 + nt * 8;
                b[nt][0] = Bs[(nr + lr) * 132 + k0 + lc    ];
                b[nt][1] = Bs[(nr + lr) * 132 + k0 + lc + 4];
            }
            #pragma unroll
            for (int mt = 0; mt < 2; mt++)
                #pragma unroll
                for (int nt = 0; nt < 2; nt++) {
                    asm volatile(
                        "mma.sync.aligned.m16n8k8.row.col.f32.tf32.tf32.f32 "
                        "{%0,%1,%2,%3}, {%4,%5,%6,%7}, {%8,%9}, {%0,%1,%2,%3};\n"
                        : "+f"(acc[mt][nt][0]), "+f"(acc[mt][nt][1]),
                          "+f"(acc[mt][nt][2]), "+f"(acc[mt][nt][3])
                        : "r"(a[mt][0]), "r"(a[mt][1]), "r"(a[mt][2]), "r"(a[mt][3]),
                          "r"(b[nt][0]), "r"(b[nt][1]));
                }
        }

        #pragma unroll
        for (int mt = 0; mt < 2; mt++) {
            #pragma unroll
            for (int nt = 0; nt < 2; nt++) {
                int o = wn * 16 + nt * 8 + 2 * lc;
                float bo0 = __ldg(&b3[o]), bo1 = __ldg(&b3[o + 1]);
                #pragma unroll
                for (int rr = 0; rr < 2; rr++) {
                    int row = wm * 32 + mt * 16 + lr + rr * 8;
                    int s = row >> 4, pos = row & 15;
                    float* fo = g_feat + (size_t)(n0 + s) * NFLAT;
                    float v0 = fmaxf(acc[mt][nt][rr * 2    ] + bo0, 0.f);
                    float v1 = fmaxf(acc[mt][nt][rr * 2 + 1] + bo1, 0.f);
                    fo[o * 16 + pos]       = __uint_as_float(f2tf(v0));
                    fo[(o + 1) * 16 + pos] = __uint_as_float(f2tf(v1));
                }
            }
        }
    }
}

// ---------------- Kernel 2: tf32 tensor-core GEMM, 3-stage cp.async ----------------
#define GSTAGE 3
#define GSTRIDE 2560
#define G_SMEM_BYTES (GSTAGE * 2 * GSTRIDE * 4)

__global__ __launch_bounds__(256, 2) void gemm_pre_kernel()
{
    extern __shared__ __align__(16) unsigned smg[];
    unsigned* sA = smg;
    unsigned* sB = smg + GSTAGE * GSTRIDE;

    const int tid  = threadIdx.x;
    const int lane = tid & 31;
    const int wid  = tid >> 5;
    const int lr = lane >> 2, lc = lane & 3;
    const int wm = wid & 1;
    const int wn = wid >> 1;
    const int row0 = blockIdx.y * 128;
    const int col0 = blockIdx.x * 128;

    const unsigned baseA = smem_u32(sA);
    const unsigned baseB = smem_u32(sB);

    int sm0 = (tid        ) >> 2, sk0 = ((tid      ) & 3) * 4;
    int sm1 = (tid + 256  ) >> 2, sk1 = ((tid + 256) & 3) * 4;

    float acc[4][4][4];
    #pragma unroll
    for (int mt = 0; mt < 4; mt++)
        #pragma unroll
        for (int nt = 0; nt < 4; nt++)
            #pragma unroll
            for (int r = 0; r < 4; r++) acc[mt][nt][r] = 0.f;

    #define G_ISSUE(s, kt)                                                          \
    {                                                                               \
        const float* ga0 = g_feat + (size_t)(row0 + sm0) * NFLAT + (kt) + sk0;      \
        const float* ga1 = g_feat + (size_t)(row0 + sm1) * NFLAT + (kt) + sk1;      \
        const float* gb0 = g_wih  + (size_t)(col0 + sm0) * NFLAT + (kt) + sk0;      \
        const float* gb1 = g_wih  + (size_t)(col0 + sm1) * NFLAT + (kt) + sk1;      \
        unsigned da0 = baseA + ((s)*GSTRIDE + sm0*20 + sk0) * 4;                    \
        unsigned da1 = baseA + ((s)*GSTRIDE + sm1*20 + sk1) * 4;                    \
        unsigned db0 = baseB + ((s)*GSTRIDE + sm0*20 + sk0) * 4;                    \
        unsigned db1 = baseB + ((s)*GSTRIDE + sm1*20 + sk1) * 4;                    \
        asm volatile("cp.async.cg.shared.global [%0], [%1], 16;" :: "r"(da0), "l"(ga0)); \
        asm volatile("cp.async.cg.shared.global [%0], [%1], 16;" :: "r"(da1), "l"(ga1)); \
        asm volatile("cp.async.cg.shared.global [%0], [%1], 16;" :: "r"(db0), "l"(gb0)); \
        asm volatile("cp.async.cg.shared.global [%0], [%1], 16;" :: "r"(db1), "l"(gb1)); \
    }

    G_ISSUE(0, 0);
    asm volatile("cp.async.commit_group;");
    G_ISSUE(1, 16);
    asm volatile("cp.async.commit_group;");

    const int NIT = NFLAT / 16;
    for (int it = 0; it < NIT; it++) {
        const int s = it % GSTAGE;
        asm volatile("cp.async.wait_group 1;");
        __syncthreads();
        if (it + 2 < NIT) {
            G_ISSUE((it + 2) % GSTAGE, (it + 2) * 16);
        }
        asm volatile("cp.async.commit_group;");

        const unsigned* pA = sA + s * GSTRIDE;
        const unsigned* pB = sB + s * GSTRIDE;
        #pragma unroll
        for (int ks = 0; ks < 2; ks++) {
            const int k0 = ks * 8;
            unsigned a[4][4], b[4][2];
            #pragma unroll
            for (int mt = 0; mt < 4; mt++) {
                int m0 = wm * 64 + mt * 16;
                a[mt][0] = pA[(m0 + lr    ) * 20 + k0 + lc    ];
                a[mt][1] = pA[(m0 + lr + 8) * 20 + k0 + lc    ];
                a[mt][2] = pA[(m0 + lr    ) * 20 + k0 + lc + 4];
                a[mt][3] = pA[(m0 + lr + 8) * 20 + k0 + lc + 4];
            }
            #pragma unroll
            for (int nt = 0; nt < 4; nt++) {
                int n0 = wn * 32 + nt * 8;
                b[nt][0] = pB[(n0 + lr) * 20 + k0 + lc    ];
                b[nt][1] = pB[(n0 + lr) * 20 + k0 + lc + 4];
            }
            #pragma unroll
            for (int mt = 0; mt < 4; mt++)
                #pragma unroll
                for (int nt = 0; nt < 4; nt++) {
                    asm volatile(
                        "mma.sync.aligned.m16n8k8.row.col.f32.tf32.tf32.f32 "
                        "{%0,%1,%2,%3}, {%4,%5,%6,%7}, {%8,%9}, {%0,%1,%2,%3};\n"
                        : "+f"(acc[mt][nt][0]), "+f"(acc[mt][nt][1]),
                          "+f"(acc[mt][nt][2]), "+f"(acc[mt][nt][3])
                        : "r"(a[mt][0]), "r"(a[mt][1]), "r"(a[mt][2]), "r"(a[mt][3]),
                          "r"(b[nt][0]), "r"(b[nt][1]));
                }
        }
    }

    float bb0[4], bb1[4];
    #pragma unroll
    for (int nt = 0; nt < 4; nt++) {
        int col = col0 + wn * 32 + nt * 8 + 2 * lc;
        bb0[nt] = g_bias[col];
        bb1[nt] = g_bias[col + 1];
    }
    #pragma unroll
    for (int mt = 0; mt < 4; mt++) {
        int r0 = row0 + wm * 64 + mt * 16 + lr;
        #pragma unroll
        for (int nt = 0; nt < 4; nt++) {
            int col = col0 + wn * 32 + nt * 8 + 2 * lc;
            *(float2*)&g_pre[(size_t)r0 * G4 + col] =
                make_float2(acc[mt][nt][0] + bb0[nt], acc[mt][nt][1] + bb1[nt]);
            *(float2*)&g_pre[(size_t)(r0 + 8) * G4 + col] =
                make_float2(acc[mt][nt][2] + bb0[nt], acc[mt][nt][3] + bb1[nt]);
        }
    }
}

// ---------------- Kernel 3: persistent LSTM ----------------
// RC=32 weights in registers (explicit budget: 32 wc + 2 acc + 12 f4-temps
// + addressing ~= 75 regs < 128 cap) + float4 LDS/LDG for the rest.
#define RC 32
__global__ __launch_bounds__(512, 1) void lstm_kernel(
    const float* __restrict__ done,
    const float* __restrict__ h0, const float* __restrict__ c0,
    const float* __restrict__ w_hh,
    float* __restrict__ hT, float* __restrict__ cT)
{
    __shared__ __align__(16) float hs[2][128];
    __shared__ __align__(16) float cs[2][128];
    __shared__ float gs[2][512];

    const int tid = threadIdx.x;
    const int b0  = blockIdx.x * 2;

    if (tid < 256) {
        int r = tid >> 7, u = tid & 127;
        float m = 1.f - done[b0 + r];
        hs[r][u] = h0[(b0 + r) * HID + u] * m;
        cs[r][u] = c0[(b0 + r) * HID + u] * m;
    }

    const float* wrow = w_hh + (size_t)tid * HID;
    float wc[RC];
    #pragma unroll
    for (int k = 0; k < RC; k++) wc[k] = wrow[k];
    __syncthreads();

    float a0 = g_pre[(size_t)b0 * G4 + tid];
    float a1 = g_pre[(size_t)(b0 + 1) * G4 + tid];

    for (int t = 0; t < TT; t++) {
        #pragma unroll
        for (int k = 0; k < RC; k += 4) {
            float4 h0v = *(const float4*)&hs[0][k];
            float4 h1v = *(const float4*)&hs[1][k];
            a0 = fmaf(wc[k    ], h0v.x, a0);
            a0 = fmaf(wc[k + 1], h0v.y, a0);
            a0 = fmaf(wc[k + 2], h0v.z, a0);
            a0 = fmaf(wc[k + 3], h0v.w, a0);
            a1 = fmaf(wc[k    ], h1v.x, a1);
            a1 = fmaf(wc[k + 1], h1v.y, a1);
            a1 = fmaf(wc[k + 2], h1v.z, a1);
            a1 = fmaf(wc[k + 3], h1v.w, a1);
        }
        #pragma unroll
        for (int k = RC; k < HID; k += 4) {
            float4 wv  = *(const float4*)(wrow + k);
            float4 h0v = *(const float4*)&hs[0][k];
            float4 h1v = *(const float4*)&hs[1][k];
            a0 = fmaf(wv.x, h0v.x, a0);
            a0 = fmaf(wv.y, h0v.y, a0);
            a0 = fmaf(wv.z, h0v.z, a0);
            a0 = fmaf(wv.w, h0v.w, a0);
            a1 = fmaf(wv.x, h1v.x, a1);
            a1 = fmaf(wv.y, h1v.y, a1);
            a1 = fmaf(wv.z, h1v.z, a1);
            a1 = fmaf(wv.w, h1v.w, a1);
        }
        gs[0][tid] = a0;
        gs[1][tid] = a1;

        if (t + 1 < TT) {
            a0 = g_pre[((size_t)((t + 1) * BB + b0    )) * G4 + tid];
            a1 = g_pre[((size_t)((t + 1) * BB + b0 + 1)) * G4 + tid];
        }
        __syncthreads();

        if (tid < 256) {
            int r = tid >> 7, u = tid & 127;
            float ig = fast_sigmoid(gs[r][u]);
            float fg = fast_sigmoid(gs[r][128 + u]);
            float gg = fast_tanh(gs[r][256 + u]);
            float og = fast_sigmoid(gs[r][384 + u]);
            float c = fg * cs[r][u] + ig * gg;
            float h = og * fast_tanh(c);
            g_hid[((size_t)(t * BB + b0 + r)) * HID + u] = h;
            float m = (t + 1 < TT) ? (1.f - done[(t + 1) * BB + b0 + r]) : 1.f;
            cs[r][u] = c * m;
            hs[r][u] = h * m;
        }
        __syncthreads();
    }

    if (tid < 256) {
        int r = tid >> 7, u = tid & 127;
        hT[(b0 + r) * HID + u] = hs[r][u];
        cT[(b0 + r) * HID + u] = cs[r][u];
    }
}

// ---------------- Kernel 4: heads -> out[N,8] ----------------
__global__ __launch_bounds__(128) void heads_kernel(
    const float* __restrict__ aw, const float* __restrict__ ab,
    const float* __restrict__ cw, const float* __restrict__ cb,
    float* __restrict__ out)
{
    __shared__ __align__(16) float ws [8][132];
    __shared__ __align__(16) float hsm[16][132];
    __shared__ float bs[8];

    const int tid = threadIdx.x;
    const int n0 = blockIdx.x * 16;

    for (int i = tid; i < NA * HID; i += 128) ws[i >> 7][i & 127] = aw[i];
    ws[7][tid] = cw[tid];
    if (tid < NA) bs[tid] = ab[tid];
    if (tid == NA) bs[7] = cb[0];

    for (int i = tid; i < 16 * HID; i += 128)
        hsm[i >> 7][i & 127] = g_hid[(size_t)n0 * HID + i];
    __syncthreads();

    const int s = tid >> 3, col = tid & 7;
    float acc = bs[col];
    const float4* hp = (const float4*)&hsm[s][0];
    const float4* wp = (const float4*)&ws[col][0];
    #pragma unroll
    for (int k = 0; k < 32; k++) {
        float4 h4 = hp[k], w4 = wp[k];
        acc += h4.x * w4.x + h4.y * w4.y + h4.z * w4.z + h4.w * w4.w;
    }
    out[(size_t)(n0 + s) * 8 + col] = acc;
}

// ---------------- launch ----------------
extern "C" void kernel_launch(void* const* d_in, const int* in_sizes, int n_in,
                              void* d_out, int out_size)
{
    const float* obs   = (const float*)d_in[0];
    const float* done  = (const float*)d_in[1];
    const float* h0    = (const float*)d_in[2];
    const float* c0    = (const float*)d_in[3];
    const float* w1    = (const float*)d_in[4];
    const float* b1    = (const float*)d_in[5];
    const float* w2    = (const float*)d_in[6];
    const float* b2    = (const float*)d_in[7];
    const float* w3    = (const float*)d_in[8];
    const float* b3    = (const float*)d_in[9];
    const float* w_ih  = (const float*)d_in[10];
    const float* w_hh  = (const float*)d_in[11];
    const float* b_ih  = (const float*)d_in[12];
    const float* b_hh  = (const float*)d_in[13];
    const float* aw    = (const float*)d_in[14];
    const float* ab    = (const float*)d_in[15];
    const float* cw    = (const float*)d_in[16];
    const float* cb    = (const float*)d_in[17];

    float* out = (float*)d_out;                    // [N, 8]
    float* hT  = out + (size_t)NN * 8;             // [B, HID]
    float* cT  = hT + (size_t)BB * HID;            // [B, HID]

    static bool attr_done = false;
    if (!attr_done) {
        cudaFuncSetAttribute(conv_feat_kernel,
                             cudaFuncAttributeMaxDynamicSharedMemorySize,
                             CV_SMEM_BYTES);
        cudaFuncSetAttribute(gemm_pre_kernel,
                             cudaFuncAttributeMaxDynamicSharedMemorySize,
                             G_SMEM_BYTES);
        attr_done = true;
    }

    prep_kernel<<<(G4 * NFLAT + 255) / 256, 256>>>(w_ih, b_ih, b_hh);

    conv_feat_kernel<<<NN / 4, 256, CV_SMEM_BYTES>>>(obs, w1, b1, w2, b2, w3, b3);

    dim3 ggrid(G4 / 128, NN / 128);
    gemm_pre_kernel<<<ggrid, 256, G_SMEM_BYTES>>>();

    lstm_kernel<<<BB / 2, 512>>>(done, h0, c0, w_hh, hT, cT);

    heads_kernel<<<NN / 16, 128>>>(aw, ab, cw, cb, out);
}

// round 10
// speedup vs baseline: 1.0713x; 1.0708x over previous
#include <cuda_runtime.h>
#include <cuda_bf16.h>
#include <math.h>

// Problem dims
#define TT   128
#define BB   256
#define NN   (TT*BB)        // 32768
#define HID  128
#define G4   512            // 4*HID
#define NFLAT 1024
#define NA   7

// ---------------- scratch (device globals, no allocation) ----------------
__device__ __align__(16) float g_feat[NN * NFLAT];   // tf32-rounded fp32
__device__ __align__(16) float g_pre [NN * G4];
__device__ __align__(16) float g_hid [NN * HID];
__device__ __align__(16) float g_wih [G4 * NFLAT];   // tf32-rounded fp32
__device__ __align__(16) float g_bias[G4];

__device__ __forceinline__ unsigned f2tf(float f) {
    unsigned u;
    asm("cvt.rna.tf32.f32 %0, %1;" : "=r"(u) : "f"(f));
    return u;
}
__device__ __forceinline__ unsigned smem_u32(const void* p) {
    unsigned r;
    asm("{ .reg .u64 t; cvta.to.shared.u64 t, %1; cvt.u32.u64 %0, t; }" : "=r"(r) : "l"(p));
    return r;
}
// MUFU-based tanh, overflow-safe: tanh(x) = sign(x) * (1 - t)/(1 + t), t = exp(-2|x|)
__device__ __forceinline__ float fast_tanh(float x) {
    float t = __expf(-2.f * fabsf(x));
    float r = __fdividef(1.f - t, 1.f + t);
    return copysignf(r, x);
}
__device__ __forceinline__ float fast_sigmoid(float x) {
    return __fdividef(1.f, 1.f + __expf(-x));
}

// ---------------- Kernel 0: prep (tf32 weights + fused bias) ----------------
__global__ __launch_bounds__(256) void prep_kernel(
    const float* __restrict__ wih,
    const float* __restrict__ bih, const float* __restrict__ bhh)
{
    int i = blockIdx.x * 256 + threadIdx.x;
    if (i < G4 * NFLAT) g_wih[i] = __uint_as_float(f2tf(wih[i]));
    if (i < G4)         g_bias[i] = bih[i] + bhh[i];
}

// ---------------- Kernel 1: conv stack; conv3 via tf32 mma ----------------
#define CV_XS 0
#define CV_C1 588
#define CV_S1 577
#define CV_C2 2896
#define CV_S2 801
#define CV_W2 6100
#define CV_A  8148
#define CV_B  16596
#define CV_SMEM_FLOATS (CV_B + 64*132)
#define CV_SMEM_BYTES  (CV_SMEM_FLOATS * 4)   // ~100 KB

__global__ __launch_bounds__(256) void conv_feat_kernel(
    const float* __restrict__ obs,
    const float* __restrict__ w1, const float* __restrict__ b1,
    const float* __restrict__ w2, const float* __restrict__ b2,
    const float* __restrict__ w3, const float* __restrict__ b3)
{
    extern __shared__ __align__(16) float sm[];
    const int tid = threadIdx.x;
    const int n0 = blockIdx.x * 4;

    {
        const float4* s2 = (const float4*)w2;
        float4* d2 = (float4*)(sm + CV_W2);
        for (int i = tid; i < 32*16; i += 256) d2[i] = s2[i];
        for (int i = tid; i < 64*128; i += 256) {
            int o = i >> 7, col = i & 127;
            sm[CV_B + o*132 + col] = __uint_as_float(f2tf(w3[i]));
        }
    }
    for (int i = tid; i < 4*147; i += 256) {
        int s = i / 147, r = i % 147;
        int h = r / 21, q = r % 21, w = q / 3, c = q % 3;
        sm[CV_XS + s*147 + c*49 + h*7 + w] = obs[(size_t)n0 * 147 + i];
    }
    __syncthreads();

    // conv1: 16 x 6x6, 3ch 2x2 (fp32)
    for (int i = tid; i < 4*576; i += 256) {
        int s = i / 576, r = i % 576;
        int o = r / 36, q = r % 36, y = q / 6, x = q % 6;
        float acc = __ldg(&b1[o]);
        #pragma unroll
        for (int c = 0; c < 3; c++) {
            float4 wv = *(const float4*)&w1[(o*3 + c) * 4];
            const float* xb = sm + CV_XS + s*147 + c*49 + y*7 + x;
            acc += xb[0] * wv.x + xb[1] * wv.y + xb[7] * wv.z + xb[8] * wv.w;
        }
        sm[CV_C1 + s*CV_S1 + o*36 + y*6 + x] = fmaxf(acc, 0.f);
    }
    __syncthreads();

    // conv2: 32 x 5x5, 16ch 2x2 (fp32)
    if (tid < 200) {
        int oh = tid / 100, rem = tid % 100;
        int pos = rem >> 2, s = rem & 3;
        int y = pos / 5, x = pos % 5;
        int o0 = oh * 16;
        float acc[16];
        #pragma unroll
        for (int o = 0; o < 16; o++) acc[o] = __ldg(&b2[o0 + o]);
        const float4* w2v = (const float4*)(sm + CV_W2);
        #pragma unroll 4
        for (int c = 0; c < 16; c++) {
            const float* xb = sm + CV_C1 + s*CV_S1 + c*36 + y*6 + x;
            float aa = xb[0], ab = xb[1], ac = xb[6], ad = xb[7];
            #pragma unroll
            for (int o = 0; o < 16; o++) {
                float4 wv = w2v[(o0 + o)*16 + c];
                acc[o] += aa*wv.x + ab*wv.y + ac*wv.z + ad*wv.w;
            }
        }
        #pragma unroll
        for (int o = 0; o < 16; o++)
            sm[CV_C2 + s*CV_S2 + (o0 + o)*25 + pos] = fmaxf(acc[o], 0.f);
    }
    __syncthreads();

    // im2col for conv3
    for (int i = tid; i < 64*128; i += 256) {
        int row = i >> 7, col = i & 127;
        int s = row >> 4, pos = row & 15, y = pos >> 2, x = pos & 3;
        int c = col >> 2, j = col & 3, dy = j >> 1, dx = j & 1;
        float v = sm[CV_C2 + s*CV_S2 + c*25 + (y+dy)*5 + (x+dx)];
        sm[CV_A + row*132 + col] = __uint_as_float(f2tf(v));
    }
    __syncthreads();

    // conv3 mma: [64x64] = A[64x128] @ B^T, m16n8k8 tf32
    {
        const int lane = tid & 31, wid = tid >> 5;
        const int lr = lane >> 2, lc = lane & 3;
        const int wm = wid & 1, wn = wid >> 1;
        const unsigned* As = (const unsigned*)(sm + CV_A);
        const unsigned* Bs = (const unsigned*)(sm + CV_B);

        float acc[2][2][4];
        #pragma unroll
        for (int mt = 0; mt < 2; mt++)
            #pragma unroll
            for (int nt = 0; nt < 2; nt++)
                #pragma unroll
                for (int r = 0; r < 4; r++) acc[mt][nt][r] = 0.f;

        #pragma unroll 4
        for (int ks = 0; ks < 16; ks++) {
            const int k0 = ks * 8;
            unsigned a[2][4], b[2][2];
            #pragma unroll
            for (int mt = 0; mt < 2; mt++) {
                int m0 = wm * 32 + mt * 16;
                a[mt][0] = As[(m0 + lr    ) * 132 + k0 + lc    ];
                a[mt][1] = As[(m0 + lr + 8) * 132 + k0 + lc    ];
                a[mt][2] = As[(m0 + lr    ) * 132 + k0 + lc + 4];
                a[mt][3] = As[(m0 + lr + 8) * 132 + k0 + lc + 4];
            }
            #pragma unroll
            for (int nt = 0; nt < 2; nt++) {
                int nr = wn * 16 + nt * 8;
                b[nt][0] = Bs[(nr + lr) * 132 + k0 + lc    ];
                b[nt][1] = Bs[(nr + lr) * 132 + k0 + lc + 4];
            }
            #pragma unroll
            for (int mt = 0; mt < 2; mt++)
                #pragma unroll
                for (int nt = 0; nt < 2; nt++) {
                    asm volatile(
                        "mma.sync.aligned.m16n8k8.row.col.f32.tf32.tf32.f32 "
                        "{%0,%1,%2,%3}, {%4,%5,%6,%7}, {%8,%9}, {%0,%1,%2,%3};\n"
                        : "+f"(acc[mt][nt][0]), "+f"(acc[mt][nt][1]),
                          "+f"(acc[mt][nt][2]), "+f"(acc[mt][nt][3])
                        : "r"(a[mt][0]), "r"(a[mt][1]), "r"(a[mt][2]), "r"(a[mt][3]),
                          "r"(b[nt][0]), "r"(b[nt][1]));
                }
        }

        #pragma unroll
        for (int mt = 0; mt < 2; mt++) {
            #pragma unroll
            for (int nt = 0; nt < 2; nt++) {
                int o = wn * 16 + nt * 8 + 2 * lc;
                float bo0 = __ldg(&b3[o]), bo1 = __ldg(&b3[o + 1]);
                #pragma unroll
                for (int rr = 0; rr < 2; rr++) {
                    int row = wm * 32 + mt * 16 + lr + rr * 8;
                    int s = row >> 4, pos = row & 15;
                    float* fo = g_feat + (size_t)(n0 + s) * NFLAT;
                    float v0 = fmaxf(acc[mt][nt][rr * 2    ] + bo0, 0.f);
                    float v1 = fmaxf(acc[mt][nt][rr * 2 + 1] + bo1, 0.f);
                    fo[o * 16 + pos]       = __uint_as_float(f2tf(v0));
                    fo[(o + 1) * 16 + pos] = __uint_as_float(f2tf(v1));
                }
            }
        }
    }
}

// ---------------- Kernel 2: tf32 tensor-core GEMM, BK=32, 3-stage cp.async ----------------
// 32 K-iterations (was 64): half the wait_group/__syncthreads events.
// smem [row][36]: (4m+k) mod 32 is a lane permutation for fragment loads.
#define GSTAGE 3
#define GSTRIDE (128*36)                 // 4608 unsigned per operand per stage
#define G_SMEM_BYTES (GSTAGE * 2 * GSTRIDE * 4)   // 110592 B; x2 CTAs = 216KB < 228KB

__global__ __launch_bounds__(256, 2) void gemm_pre_kernel()
{
    extern __shared__ __align__(16) unsigned smg[];
    unsigned* sA = smg;
    unsigned* sB = smg + GSTAGE * GSTRIDE;

    const int tid  = threadIdx.x;
    const int lane = tid & 31;
    const int wid  = tid >> 5;
    const int lr = lane >> 2, lc = lane & 3;
    const int wm = wid & 1;
    const int wn = wid >> 1;
    const int row0 = blockIdx.y * 128;
    const int col0 = blockIdx.x * 128;

    const unsigned baseA = smem_u32(sA);
    const unsigned baseB = smem_u32(sB);

    float acc[4][4][4];
    #pragma unroll
    for (int mt = 0; mt < 4; mt++)
        #pragma unroll
        for (int nt = 0; nt < 4; nt++)
            #pragma unroll
            for (int r = 0; r < 4; r++) acc[mt][nt][r] = 0.f;

    // staging: 128 rows x 32 k per operand per stage = 4096 floats = 16/thread
    // chunk c in 0..3: idx = tid + c*256; m = idx/8; kq = (idx%8)*4
    #define G_ISSUE(s, kt)                                                              \
    {                                                                                   \
        _Pragma("unroll")                                                               \
        for (int c = 0; c < 4; c++) {                                                   \
            int idx = tid + c * 256;                                                    \
            int m = idx >> 3, kq = (idx & 7) * 4;                                       \
            const float* ga = g_feat + (size_t)(row0 + m) * NFLAT + (kt) + kq;          \
            const float* gb = g_wih  + (size_t)(col0 + m) * NFLAT + (kt) + kq;          \
            unsigned da = baseA + ((s)*GSTRIDE + m*36 + kq) * 4;                        \
            unsigned db = baseB + ((s)*GSTRIDE + m*36 + kq) * 4;                        \
            asm volatile("cp.async.cg.shared.global [%0], [%1], 16;" :: "r"(da), "l"(ga)); \
            asm volatile("cp.async.cg.shared.global [%0], [%1], 16;" :: "r"(db), "l"(gb)); \
        }                                                                               \
    }

    G_ISSUE(0, 0);
    asm volatile("cp.async.commit_group;");
    G_ISSUE(1, 32);
    asm volatile("cp.async.commit_group;");

    const int NIT = NFLAT / 32;   // 32
    for (int it = 0; it < NIT; it++) {
        const int s = it % GSTAGE;
        asm volatile("cp.async.wait_group 1;");
        __syncthreads();
        if (it + 2 < NIT) {
            G_ISSUE((it + 2) % GSTAGE, (it + 2) * 32);
        }
        asm volatile("cp.async.commit_group;");

        const unsigned* pA = sA + s * GSTRIDE;
        const unsigned* pB = sB + s * GSTRIDE;
        #pragma unroll
        for (int ks = 0; ks < 4; ks++) {
            const int k0 = ks * 8;
            unsigned a[4][4], b[4][2];
            #pragma unroll
            for (int mt = 0; mt < 4; mt++) {
                int m0 = wm * 64 + mt * 16;
                a[mt][0] = pA[(m0 + lr    ) * 36 + k0 + lc    ];
                a[mt][1] = pA[(m0 + lr + 8) * 36 + k0 + lc    ];
                a[mt][2] = pA[(m0 + lr    ) * 36 + k0 + lc + 4];
                a[mt][3] = pA[(m0 + lr + 8) * 36 + k0 + lc + 4];
            }
            #pragma unroll
            for (int nt = 0; nt < 4; nt++) {
                int n0 = wn * 32 + nt * 8;
                b[nt][0] = pB[(n0 + lr) * 36 + k0 + lc    ];
                b[nt][1] = pB[(n0 + lr) * 36 + k0 + lc + 4];
            }
            #pragma unroll
            for (int mt = 0; mt < 4; mt++)
                #pragma unroll
                for (int nt = 0; nt < 4; nt++) {
                    asm volatile(
                        "mma.sync.aligned.m16n8k8.row.col.f32.tf32.tf32.f32 "
                        "{%0,%1,%2,%3}, {%4,%5,%6,%7}, {%8,%9}, {%0,%1,%2,%3};\n"
                        : "+f"(acc[mt][nt][0]), "+f"(acc[mt][nt][1]),
                          "+f"(acc[mt][nt][2]), "+f"(acc[mt][nt][3])
                        : "r"(a[mt][0]), "r"(a[mt][1]), "r"(a[mt][2]), "r"(a[mt][3]),
                          "r"(b[nt][0]), "r"(b[nt][1]));
                }
        }
    }

    float bb0[4], bb1[4];
    #pragma unroll
    for (int nt = 0; nt < 4; nt++) {
        int col = col0 + wn * 32 + nt * 8 + 2 * lc;
        bb0[nt] = g_bias[col];
        bb1[nt] = g_bias[col + 1];
    }
    #pragma unroll
    for (int mt = 0; mt < 4; mt++) {
        int r0 = row0 + wm * 64 + mt * 16 + lr;
        #pragma unroll
        for (int nt = 0; nt < 4; nt++) {
            int col = col0 + wn * 32 + nt * 8 + 2 * lc;
            *(float2*)&g_pre[(size_t)r0 * G4 + col] =
                make_float2(acc[mt][nt][0] + bb0[nt], acc[mt][nt][1] + bb1[nt]);
            *(float2*)&g_pre[(size_t)(r0 + 8) * G4 + col] =
                make_float2(acc[mt][nt][2] + bb0[nt], acc[mt][nt][3] + bb1[nt]);
        }
    }
}

// ---------------- Kernel 3: persistent LSTM (R6-exact: scalar hs, RC=64) ----------------
#define RC 64
__global__ __launch_bounds__(512, 1) void lstm_kernel(
    const float* __restrict__ done,
    const float* __restrict__ h0, const float* __restrict__ c0,
    const float* __restrict__ w_hh,
    float* __restrict__ hT, float* __restrict__ cT)
{
    __shared__ float hs[2][128];
    __shared__ float cs[2][128];
    __shared__ float gs[2][512];

    const int tid = threadIdx.x;
    const int b0  = blockIdx.x * 2;

    if (tid < 256) {
        int r = tid >> 7, u = tid & 127;
        float m = 1.f - done[b0 + r];
        hs[r][u] = h0[(b0 + r) * HID + u] * m;
        cs[r][u] = c0[(b0 + r) * HID + u] * m;
    }

    const float* wrow = w_hh + (size_t)tid * HID;
    float wc[RC];
    #pragma unroll
    for (int k = 0; k < RC; k++) wc[k] = wrow[k];
    __syncthreads();

    float a0 = g_pre[(size_t)b0 * G4 + tid];
    float a1 = g_pre[(size_t)(b0 + 1) * G4 + tid];

    for (int t = 0; t < TT; t++) {
        #pragma unroll
        for (int k = 0; k < RC; k++) {
            float w = wc[k];
            a0 = fmaf(w, hs[0][k], a0);
            a1 = fmaf(w, hs[1][k], a1);
        }
        #pragma unroll
        for (int k = RC; k < HID; k += 4) {
            float4 wv = *(const float4*)(wrow + k);
            a0 = fmaf(wv.x, hs[0][k], a0);   a0 = fmaf(wv.y, hs[0][k+1], a0);
            a0 = fmaf(wv.z, hs[0][k+2], a0); a0 = fmaf(wv.w, hs[0][k+3], a0);
            a1 = fmaf(wv.x, hs[1][k], a1);   a1 = fmaf(wv.y, hs[1][k+1], a1);
            a1 = fmaf(wv.z, hs[1][k+2], a1); a1 = fmaf(wv.w, hs[1][k+3], a1);
        }
        gs[0][tid] = a0;
        gs[1][tid] = a1;

        if (t + 1 < TT) {
            a0 = g_pre[((size_t)((t + 1) * BB + b0    )) * G4 + tid];
            a1 = g_pre[((size_t)((t + 1) * BB + b0 + 1)) * G4 + tid];
        }
        __syncthreads();

        if (tid < 256) {
            int r = tid >> 7, u = tid & 127;
            float ig = fast_sigmoid(gs[r][u]);
            float fg = fast_sigmoid(gs[r][128 + u]);
            float gg = fast_tanh(gs[r][256 + u]);
            float og = fast_sigmoid(gs[r][384 + u]);
            float c = fg * cs[r][u] + ig * gg;
            float h = og * fast_tanh(c);
            g_hid[((size_t)(t * BB + b0 + r)) * HID + u] = h;
            float m = (t + 1 < TT) ? (1.f - done[(t + 1) * BB + b0 + r]) : 1.f;
            cs[r][u] = c * m;
            hs[r][u] = h * m;
        }
        __syncthreads();
    }

    if (tid < 256) {
        int r = tid >> 7, u = tid & 127;
        hT[(b0 + r) * HID + u] = hs[r][u];
        cT[(b0 + r) * HID + u] = cs[r][u];
    }
}

// ---------------- Kernel 4: heads -> out[N,8] ----------------
__global__ __launch_bounds__(128) void heads_kernel(
    const float* __restrict__ aw, const float* __restrict__ ab,
    const float* __restrict__ cw, const float* __restrict__ cb,
    float* __restrict__ out)
{
    __shared__ __align__(16) float ws [8][132];
    __shared__ __align__(16) float hsm[16][132];
    __shared__ float bs[8];

    const int tid = threadIdx.x;
    const int n0 = blockIdx.x * 16;

    for (int i = tid; i < NA * HID; i += 128) ws[i >> 7][i & 127] = aw[i];
    ws[7][tid] = cw[tid];
    if (tid < NA) bs[tid] = ab[tid];
    if (tid == NA) bs[7] = cb[0];

    for (int i = tid; i < 16 * HID; i += 128)
        hsm[i >> 7][i & 127] = g_hid[(size_t)n0 * HID + i];
    __syncthreads();

    const int s = tid >> 3, col = tid & 7;
    float acc = bs[col];
    const float4* hp = (const float4*)&hsm[s][0];
    const float4* wp = (const float4*)&ws[col][0];
    #pragma unroll
    for (int k = 0; k < 32; k++) {
        float4 h4 = hp[k], w4 = wp[k];
        acc += h4.x * w4.x + h4.y * w4.y + h4.z * w4.z + h4.w * w4.w;
    }
    out[(size_t)(n0 + s) * 8 + col] = acc;
}

// ---------------- launch ----------------
extern "C" void kernel_launch(void* const* d_in, const int* in_sizes, int n_in,
                              void* d_out, int out_size)
{
    const float* obs   = (const float*)d_in[0];
    const float* done  = (const float*)d_in[1];
    const float* h0    = (const float*)d_in[2];
    const float* c0    = (const float*)d_in[3];
    const float* w1    = (const float*)d_in[4];
    const float* b1    = (const float*)d_in[5];
    const float* w2    = (const float*)d_in[6];
    const float* b2    = (const float*)d_in[7];
    const float* w3    = (const float*)d_in[8];
    const float* b3    = (const float*)d_in[9];
    const float* w_ih  = (const float*)d_in[10];
    const float* w_hh  = (const float*)d_in[11];
    const float* b_ih  = (const float*)d_in[12];
    const float* b_hh  = (const float*)d_in[13];
    const float* aw    = (const float*)d_in[14];
    const float* ab    = (const float*)d_in[15];
    const float* cw    = (const float*)d_in[16];
    const float* cb    = (const float*)d_in[17];

    float* out = (float*)d_out;                    // [N, 8]
    float* hT  = out + (size_t)NN * 8;             // [B, HID]
    float* cT  = hT + (size_t)BB * HID;            // [B, HID]

    static bool attr_done = false;
    if (!attr_done) {
        cudaFuncSetAttribute(conv_feat_kernel,
                             cudaFuncAttributeMaxDynamicSharedMemorySize,
                             CV_SMEM_BYTES);
        cudaFuncSetAttribute(gemm_pre_kernel,
                             cudaFuncAttributeMaxDynamicSharedMemorySize,
                             G_SMEM_BYTES);
        attr_done = true;
    }

    prep_kernel<<<(G4 * NFLAT + 255) / 256, 256>>>(w_ih, b_ih, b_hh);

    conv_feat_kernel<<<NN / 4, 256, CV_SMEM_BYTES>>>(obs, w1, b1, w2, b2, w3, b3);

    dim3 ggrid(G4 / 128, NN / 128);
    gemm_pre_kernel<<<ggrid, 256, G_SMEM_BYTES>>>();

    lstm_kernel<<<BB / 2, 512>>>(done, h0, c0, w_hh, hT, cT);

    heads_kernel<<<NN / 16, 128>>>(aw, ab, cw, cb, out);
}

// round 12
// speedup vs baseline: 1.1103x; 1.0364x over previous
#include <cuda_runtime.h>
#include <cuda_bf16.h>
#include <math.h>
#include <stdint.h>

// Problem dims
#define TT   128
#define BB   256
#define NN   (TT*BB)        // 32768
#define HID  128
#define G4   512            // 4*HID
#define NFLAT 1024
#define NA   7

// NOTE (R10 finding): this harness emits compute_103 PTX; ptxas rejects ALL
// tcgen05/.kind::tf32 instructions on plain sm_103. mma.sync is the tensor
// ceiling reachable in this bench.

// ---------------- scratch (device globals, no allocation) ----------------
__device__ __align__(16) float g_feat[NN * NFLAT];   // tf32-rounded fp32
__device__ __align__(16) float g_pre [NN * G4];
__device__ __align__(16) float g_wih [G4 * NFLAT];   // tf32-rounded fp32
__device__ __align__(16) float g_bias[G4];

__device__ __forceinline__ unsigned f2tf(float f) {
    unsigned u;
    asm("cvt.rna.tf32.f32 %0, %1;" : "=r"(u) : "f"(f));
    return u;
}
__device__ __forceinline__ unsigned smem_u32(const void* p) {
    unsigned r;
    asm("{ .reg .u64 t; cvta.to.shared.u64 t, %1; cvt.u32.u64 %0, t; }" : "=r"(r) : "l"(p));
    return r;
}
// MUFU-based tanh, overflow-safe: tanh(x) = sign(x) * (1 - t)/(1 + t), t = exp(-2|x|)
__device__ __forceinline__ float fast_tanh(float x) {
    float t = __expf(-2.f * fabsf(x));
    float r = __fdividef(1.f - t, 1.f + t);
    return copysignf(r, x);
}
__device__ __forceinline__ float fast_sigmoid(float x) {
    return __fdividef(1.f, 1.f + __expf(-x));
}

// ---------------- Kernel 0: prep (tf32 weights + fused bias, float4) ----------------
__global__ __launch_bounds__(256) void prep_kernel(
    const float* __restrict__ wih,
    const float* __restrict__ bih, const float* __restrict__ bhh)
{
    int i = blockIdx.x * 256 + threadIdx.x;
    if (i < G4 * NFLAT / 4) {
        float4 v = *(const float4*)&wih[i * 4];
        v.x = __uint_as_float(f2tf(v.x));
        v.y = __uint_as_float(f2tf(v.y));
        v.z = __uint_as_float(f2tf(v.z));
        v.w = __uint_as_float(f2tf(v.w));
        *(float4*)&g_wih[i * 4] = v;
    }
    if (i < G4) g_bias[i] = bih[i] + bhh[i];
}

// ---------------- Kernel 1: conv stack; conv3 via tf32 mma (R9-exact) ----------------
#define CV_XS 0
#define CV_C1 588
#define CV_S1 577
#define CV_C2 2896
#define CV_S2 801
#define CV_W2 6100
#define CV_A  8148
#define CV_B  16596
#define CV_SMEM_FLOATS (CV_B + 64*132)
#define CV_SMEM_BYTES  (CV_SMEM_FLOATS * 4)   // ~100 KB

__global__ __launch_bounds__(256) void conv_feat_kernel(
    const float* __restrict__ obs,
    const float* __restrict__ w1, const float* __restrict__ b1,
    const float* __restrict__ w2, const float* __restrict__ b2,
    const float* __restrict__ w3, const float* __restrict__ b3)
{
    extern __shared__ __align__(16) float sm[];
    const int tid = threadIdx.x;
    const int n0 = blockIdx.x * 4;

    {
        const float4* s2 = (const float4*)w2;
        float4* d2 = (float4*)(sm + CV_W2);
        for (int i = tid; i < 32*16; i += 256) d2[i] = s2[i];
        for (int i = tid; i < 64*128; i += 256) {
            int o = i >> 7, col = i & 127;
            sm[CV_B + o*132 + col] = __uint_as_float(f2tf(w3[i]));
        }
    }
    for (int i = tid; i < 4*147; i += 256) {
        int s = i / 147, r = i % 147;
        int h = r / 21, q = r % 21, w = q / 3, c = q % 3;
        sm[CV_XS + s*147 + c*49 + h*7 + w] = obs[(size_t)n0 * 147 + i];
    }
    __syncthreads();

    // conv1: 16 x 6x6, 3ch 2x2 (fp32)
    for (int i = tid; i < 4*576; i += 256) {
        int s = i / 576, r = i % 576;
        int o = r / 36, q = r % 36, y = q / 6, x = q % 6;
        float acc = __ldg(&b1[o]);
        #pragma unroll
        for (int c = 0; c < 3; c++) {
            float4 wv = *(const float4*)&w1[(o*3 + c) * 4];
            const float* xb = sm + CV_XS + s*147 + c*49 + y*7 + x;
            acc += xb[0] * wv.x + xb[1] * wv.y + xb[7] * wv.z + xb[8] * wv.w;
        }
        sm[CV_C1 + s*CV_S1 + o*36 + y*6 + x] = fmaxf(acc, 0.f);
    }
    __syncthreads();

    // conv2: 32 x 5x5, 16ch 2x2 (fp32)
    if (tid < 200) {
        int oh = tid / 100, rem = tid % 100;
        int pos = rem >> 2, s = rem & 3;
        int y = pos / 5, x = pos % 5;
        int o0 = oh * 16;
        float acc[16];
        #pragma unroll
        for (int o = 0; o < 16; o++) acc[o] = __ldg(&b2[o0 + o]);
        const float4* w2v = (const float4*)(sm + CV_W2);
        #pragma unroll 4
        for (int c = 0; c < 16; c++) {
            const float* xb = sm + CV_C1 + s*CV_S1 + c*36 + y*6 + x;
            float aa = xb[0], ab = xb[1], ac = xb[6], ad = xb[7];
            #pragma unroll
            for (int o = 0; o < 16; o++) {
                float4 wv = w2v[(o0 + o)*16 + c];
                acc[o] += aa*wv.x + ab*wv.y + ac*wv.z + ad*wv.w;
            }
        }
        #pragma unroll
        for (int o = 0; o < 16; o++)
            sm[CV_C2 + s*CV_S2 + (o0 + o)*25 + pos] = fmaxf(acc[o], 0.f);
    }
    __syncthreads();

    // im2col for conv3
    for (int i = tid; i < 64*128; i += 256) {
        int row = i >> 7, col = i & 127;
        int s = row >> 4, pos = row & 15, y = pos >> 2, x = pos & 3;
        int c = col >> 2, j = col & 3, dy = j >> 1, dx = j & 1;
        float v = sm[CV_C2 + s*CV_S2 + c*25 + (y+dy)*5 + (x+dx)];
        sm[CV_A + row*132 + col] = __uint_as_float(f2tf(v));
    }
    __syncthreads();

    // conv3 mma: [64x64] = A[64x128] @ B^T, m16n8k8 tf32
    {
        const int lane = tid & 31, wid = tid >> 5;
        const int lr = lane >> 2, lc = lane & 3;
        const int wm = wid & 1, wn = wid >> 1;
        const unsigned* As = (const unsigned*)(sm + CV_A);
        const unsigned* Bs = (const unsigned*)(sm + CV_B);

        float acc[2][2][4];
        #pragma unroll
        for (int mt = 0; mt < 2; mt++)
            #pragma unroll
            for (int nt = 0; nt < 2; nt++)
                #pragma unroll
                for (int r = 0; r < 4; r++) acc[mt][nt][r] = 0.f;

        #pragma unroll 4
        for (int ks = 0; ks < 16; ks++) {
            const int k0 = ks * 8;
            unsigned a[2][4], b[2][2];
            #pragma unroll
            for (int mt = 0; mt < 2; mt++) {
                int m0 = wm * 32 + mt * 16;
                a[mt][0] = As[(m0 + lr    ) * 132 + k0 + lc    ];
                a[mt][1] = As[(m0 + lr + 8) * 132 + k0 + lc    ];
                a[mt][2] = As[(m0 + lr    ) * 132 + k0 + lc + 4];
                a[mt][3] = As[(m0 + lr + 8) * 132 + k0 + lc + 4];
            }
            #pragma unroll
            for (int nt = 0; nt < 2; nt++) {
                int nr = wn * 16 + nt * 8;
                b[nt][0] = Bs[(nr + lr) * 132 + k0 + lc    ];
                b[nt][1] = Bs[(nr + lr) * 132 + k0 + lc + 4];
            }
            #pragma unroll
            for (int mt = 0; mt < 2; mt++)
                #pragma unroll
                for (int nt = 0; nt < 2; nt++) {
                    asm volatile(
                        "mma.sync.aligned.m16n8k8.row.col.f32.tf32.tf32.f32 "
                        "{%0,%1,%2,%3}, {%4,%5,%6,%7}, {%8,%9}, {%0,%1,%2,%3};\n"
                        : "+f"(acc[mt][nt][0]), "+f"(acc[mt][nt][1]),
                          "+f"(acc[mt][nt][2]), "+f"(acc[mt][nt][3])
                        : "r"(a[mt][0]), "r"(a[mt][1]), "r"(a[mt][2]), "r"(a[mt][3]),
                          "r"(b[nt][0]), "r"(b[nt][1]));
                }
        }

        #pragma unroll
        for (int mt = 0; mt < 2; mt++) {
            #pragma unroll
            for (int nt = 0; nt < 2; nt++) {
                int o = wn * 16 + nt * 8 + 2 * lc;
                float bo0 = __ldg(&b3[o]), bo1 = __ldg(&b3[o + 1]);
                #pragma unroll
                for (int rr = 0; rr < 2; rr++) {
                    int row = wm * 32 + mt * 16 + lr + rr * 8;
                    int s = row >> 4, pos = row & 15;
                    float* fo = g_feat + (size_t)(n0 + s) * NFLAT;
                    float v0 = fmaxf(acc[mt][nt][rr * 2    ] + bo0, 0.f);
                    float v1 = fmaxf(acc[mt][nt][rr * 2 + 1] + bo1, 0.f);
                    fo[o * 16 + pos]       = __uint_as_float(f2tf(v0));
                    fo[(o + 1) * 16 + pos] = __uint_as_float(f2tf(v1));
                }
            }
        }
    }
}

// ---------------- Kernel 2: tf32 mma.sync GEMM, BK=32, 3-stage cp.async (R9-exact) ----------------
#define GSTAGE 3
#define GSTRIDE (128*36)
#define G_SMEM_BYTES (GSTAGE * 2 * GSTRIDE * 4)   // 110592 B; x2 CTAs = 216KB < 228KB

__global__ __launch_bounds__(256, 2) void gemm_pre_kernel()
{
    extern __shared__ __align__(16) unsigned smg[];
    unsigned* sA = smg;
    unsigned* sB = smg + GSTAGE * GSTRIDE;

    const int tid  = threadIdx.x;
    const int lane = tid & 31;
    const int wid  = tid >> 5;
    const int lr = lane >> 2, lc = lane & 3;
    const int wm = wid & 1;
    const int wn = wid >> 1;
    const int row0 = blockIdx.y * 128;
    const int col0 = blockIdx.x * 128;

    const unsigned baseA = smem_u32(sA);
    const unsigned baseB = smem_u32(sB);

    float acc[4][4][4];
    #pragma unroll
    for (int mt = 0; mt < 4; mt++)
        #pragma unroll
        for (int nt = 0; nt < 4; nt++)
            #pragma unroll
            for (int r = 0; r < 4; r++) acc[mt][nt][r] = 0.f;

    #define G_ISSUE(s, kt)                                                              \
    {                                                                                   \
        _Pragma("unroll")                                                               \
        for (int c = 0; c < 4; c++) {                                                   \
            int idx = tid + c * 256;                                                    \
            int m = idx >> 3, kq = (idx & 7) * 4;                                       \
            const float* ga = g_feat + (size_t)(row0 + m) * NFLAT + (kt) + kq;          \
            const float* gb = g_wih  + (size_t)(col0 + m) * NFLAT + (kt) + kq;          \
            unsigned da = baseA + ((s)*GSTRIDE + m*36 + kq) * 4;                        \
            unsigned db = baseB + ((s)*GSTRIDE + m*36 + kq) * 4;                        \
            asm volatile("cp.async.cg.shared.global [%0], [%1], 16;" :: "r"(da), "l"(ga)); \
            asm volatile("cp.async.cg.shared.global [%0], [%1], 16;" :: "r"(db), "l"(gb)); \
        }                                                                               \
    }

    G_ISSUE(0, 0);
    asm volatile("cp.async.commit_group;");
    G_ISSUE(1, 32);
    asm volatile("cp.async.commit_group;");

    const int NIT = NFLAT / 32;   // 32
    for (int it = 0; it < NIT; it++) {
        const int s = it % GSTAGE;
        asm volatile("cp.async.wait_group 1;");
        __syncthreads();
        if (it + 2 < NIT) {
            G_ISSUE((it + 2) % GSTAGE, (it + 2) * 32);
        }
        asm volatile("cp.async.commit_group;");

        const unsigned* pA = sA + s * GSTRIDE;
        const unsigned* pB = sB + s * GSTRIDE;
        #pragma unroll
        for (int ks = 0; ks < 4; ks++) {
            const int k0 = ks * 8;
            unsigned a[4][4], b[4][2];
            #pragma unroll
            for (int mt = 0; mt < 4; mt++) {
                int m0 = wm * 64 + mt * 16;
                a[mt][0] = pA[(m0 + lr    ) * 36 + k0 + lc    ];
                a[mt][1] = pA[(m0 + lr + 8) * 36 + k0 + lc    ];
                a[mt][2] = pA[(m0 + lr    ) * 36 + k0 + lc + 4];
                a[mt][3] = pA[(m0 + lr + 8) * 36 + k0 + lc + 4];
            }
            #pragma unroll
            for (int nt = 0; nt < 4; nt++) {
                int n0 = wn * 32 + nt * 8;
                b[nt][0] = pB[(n0 + lr) * 36 + k0 + lc    ];
                b[nt][1] = pB[(n0 + lr) * 36 + k0 + lc + 4];
            }
            #pragma unroll
            for (int mt = 0; mt < 4; mt++)
                #pragma unroll
                for (int nt = 0; nt < 4; nt++) {
                    asm volatile(
                        "mma.sync.aligned.m16n8k8.row.col.f32.tf32.tf32.f32 "
                        "{%0,%1,%2,%3}, {%4,%5,%6,%7}, {%8,%9}, {%0,%1,%2,%3};\n"
                        : "+f"(acc[mt][nt][0]), "+f"(acc[mt][nt][1]),
                          "+f"(acc[mt][nt][2]), "+f"(acc[mt][nt][3])
                        : "r"(a[mt][0]), "r"(a[mt][1]), "r"(a[mt][2]), "r"(a[mt][3]),
                          "r"(b[nt][0]), "r"(b[nt][1]));
                }
        }
    }

    float bb0[4], bb1[4];
    #pragma unroll
    for (int nt = 0; nt < 4; nt++) {
        int col = col0 + wn * 32 + nt * 8 + 2 * lc;
        bb0[nt] = g_bias[col];
        bb1[nt] = g_bias[col + 1];
    }
    #pragma unroll
    for (int mt = 0; mt < 4; mt++) {
        int r0 = row0 + wm * 64 + mt * 16 + lr;
        #pragma unroll
        for (int nt = 0; nt < 4; nt++) {
            int col = col0 + wn * 32 + nt * 8 + 2 * lc;
            *(float2*)&g_pre[(size_t)r0 * G4 + col] =
                make_float2(acc[mt][nt][0] + bb0[nt], acc[mt][nt][1] + bb1[nt]);
            *(float2*)&g_pre[(size_t)(r0 + 8) * G4 + col] =
                make_float2(acc[mt][nt][2] + bb0[nt], acc[mt][nt][3] + bb1[nt]);
        }
    }
}

// ---------------- Kernel 3: persistent LSTM + fused heads ----------------
// Core matvec/gate structure = R9 (measured 298us). New: threads 256-511,
// idle during the gate phase, compute the heads GEMV for step t-1 from a
// double-buffered unmasked-h (ho). Deletes heads_kernel + g_hid entirely.
#define RC 64
__global__ __launch_bounds__(512, 1) void lstm_kernel(
    const float* __restrict__ done,
    const float* __restrict__ h0, const float* __restrict__ c0,
    const float* __restrict__ w_hh,
    const float* __restrict__ aw, const float* __restrict__ ab,
    const float* __restrict__ cw, const float* __restrict__ cb,
    float* __restrict__ out,
    float* __restrict__ hT, float* __restrict__ cT)
{
    __shared__ float hs[2][128];
    __shared__ float cs[2][128];
    __shared__ float gs[2][512];
    __shared__ float ho[2][2][128];     // [t&1][row][unit], unmasked h
    __shared__ float hw[8][128];        // rows 0-6 actor, row 7 critic
    __shared__ float hb[8];

    const int tid = threadIdx.x;
    const int b0  = blockIdx.x * 2;

    if (tid < 256) {
        int r = tid >> 7, u = tid & 127;
        float m = 1.f - done[b0 + r];
        hs[r][u] = h0[(b0 + r) * HID + u] * m;
        cs[r][u] = c0[(b0 + r) * HID + u] * m;
    }
    // heads weights/bias
    for (int i = tid; i < 8 * 128; i += 512) {
        int row = i >> 7, u = i & 127;
        hw[row][u] = (row < NA) ? aw[i] : cw[u];
    }
    if (tid < NA) hb[tid] = ab[tid];
    if (tid == NA) hb[NA] = cb[0];

    const float* wrow = w_hh + (size_t)tid * HID;
    float wc[RC];
    #pragma unroll
    for (int k = 0; k < RC; k++) wc[k] = wrow[k];
    __syncthreads();

    float a0 = g_pre[(size_t)b0 * G4 + tid];
    float a1 = g_pre[(size_t)(b0 + 1) * G4 + tid];

    for (int t = 0; t < TT; t++) {
        #pragma unroll
        for (int k = 0; k < RC; k++) {
            float w = wc[k];
            a0 = fmaf(w, hs[0][k], a0);
            a1 = fmaf(w, hs[1][k], a1);
        }
        #pragma unroll
        for (int k = RC; k < HID; k += 4) {
            float4 wv = *(const float4*)(wrow + k);
            a0 = fmaf(wv.x, hs[0][k], a0);   a0 = fmaf(wv.y, hs[0][k+1], a0);
            a0 = fmaf(wv.z, hs[0][k+2], a0); a0 = fmaf(wv.w, hs[0][k+3], a0);
            a1 = fmaf(wv.x, hs[1][k], a1);   a1 = fmaf(wv.y, hs[1][k+1], a1);
            a1 = fmaf(wv.z, hs[1][k+2], a1); a1 = fmaf(wv.w, hs[1][k+3], a1);
        }
        gs[0][tid] = a0;
        gs[1][tid] = a1;

        if (t + 1 < TT) {
            a0 = g_pre[((size_t)((t + 1) * BB + b0    )) * G4 + tid];
            a1 = g_pre[((size_t)((t + 1) * BB + b0 + 1)) * G4 + tid];
        }
        __syncthreads();

        if (tid < 256) {
            // gate phase (unchanged math)
            int r = tid >> 7, u = tid & 127;
            float ig = fast_sigmoid(gs[r][u]);
            float fg = fast_sigmoid(gs[r][128 + u]);
            float gg = fast_tanh(gs[r][256 + u]);
            float og = fast_sigmoid(gs[r][384 + u]);
            float c = fg * cs[r][u] + ig * gg;
            float h = og * fast_tanh(c);
            ho[t & 1][r][u] = h;
            float m = (t + 1 < TT) ? (1.f - done[(t + 1) * BB + b0 + r]) : 1.f;
            cs[r][u] = c * m;
            hs[r][u] = h * m;
        } else if (t > 0) {
            // heads for step t-1 (ho[(t-1)&1] stable: written last gate phase,
            // fenced by the loop-end __syncthreads)
            int tid2 = tid - 256;
            int r = tid2 >> 7, q = tid2 & 127;
            int col = q >> 4, seg = q & 15;
            const float* hv = ho[(t - 1) & 1][r] + seg * 8;
            const float* wv = hw[col] + seg * 8;
            float p = 0.f;
            #pragma unroll
            for (int j = 0; j < 8; j++) p = fmaf(hv[j], wv[j], p);
            #pragma unroll
            for (int off = 8; off >= 1; off >>= 1)
                p += __shfl_xor_sync(0xffffffffu, p, off);
            if (seg == 0)
                out[(size_t)((t - 1) * BB + b0 + r) * 8 + col] = p + hb[col];
        }
        __syncthreads();
    }

    // heads for the final step (ho[(TT-1)&1] fenced by loop-end sync)
    if (tid < 256) {
        int r = tid >> 7, q = tid & 127;
        int col = q >> 4, seg = q & 15;
        const float* hv = ho[(TT - 1) & 1][r] + seg * 8;
        const float* wv = hw[col] + seg * 8;
        float p = 0.f;
        #pragma unroll
        for (int j = 0; j < 8; j++) p = fmaf(hv[j], wv[j], p);
        #pragma unroll
        for (int off = 8; off >= 1; off >>= 1)
            p += __shfl_xor_sync(0xffffffffu, p, off);
        if (seg == 0)
            out[(size_t)((TT - 1) * BB + b0 + r) * 8 + col] = p + hb[col];
    }

    if (tid < 256) {
        int r = tid >> 7, u = tid & 127;
        hT[(b0 + r) * HID + u] = hs[r][u];
        cT[(b0 + r) * HID + u] = cs[r][u];
    }
}

// ---------------- launch ----------------
extern "C" void kernel_launch(void* const* d_in, const int* in_sizes, int n_in,
                              void* d_out, int out_size)
{
    const float* obs   = (const float*)d_in[0];
    const float* done  = (const float*)d_in[1];
    const float* h0    = (const float*)d_in[2];
    const float* c0    = (const float*)d_in[3];
    const float* w1    = (const float*)d_in[4];
    const float* b1    = (const float*)d_in[5];
    const float* w2    = (const float*)d_in[6];
    const float* b2    = (const float*)d_in[7];
    const float* w3    = (const float*)d_in[8];
    const float* b3    = (const float*)d_in[9];
    const float* w_ih  = (const float*)d_in[10];
    const float* w_hh  = (const float*)d_in[11];
    const float* b_ih  = (const float*)d_in[12];
    const float* b_hh  = (const float*)d_in[13];
    const float* aw    = (const float*)d_in[14];
    const float* ab    = (const float*)d_in[15];
    const float* cw    = (const float*)d_in[16];
    const float* cb    = (const float*)d_in[17];

    float* out = (float*)d_out;                    // [N, 8]
    float* hT  = out + (size_t)NN * 8;             // [B, HID]
    float* cT  = hT + (size_t)BB * HID;            // [B, HID]

    static bool attr_done = false;
    if (!attr_done) {
        cudaFuncSetAttribute(conv_feat_kernel,
                             cudaFuncAttributeMaxDynamicSharedMemorySize,
                             CV_SMEM_BYTES);
        cudaFuncSetAttribute(gemm_pre_kernel,
                             cudaFuncAttributeMaxDynamicSharedMemorySize,
                             G_SMEM_BYTES);
        attr_done = true;
    }

    prep_kernel<<<(G4 * NFLAT / 4 + 255) / 256, 256>>>(w_ih, b_ih, b_hh);

    conv_feat_kernel<<<NN / 4, 256, CV_SMEM_BYTES>>>(obs, w1, b1, w2, b2, w3, b3);

    dim3 ggrid(G4 / 128, NN / 128);
    gemm_pre_kernel<<<ggrid, 256, G_SMEM_BYTES>>>();

    lstm_kernel<<<BB / 2, 512>>>(done, h0, c0, w_hh, aw, ab, cw, cb, out, hT, cT);
}